// round 1
// baseline (speedup 1.0000x reference)
#include <cuda_runtime.h>
#include <cstdint>

// KMISCoarsening: k-MIS sampling + lazy random walk multinomial clustering +
// pooling + adjacency coarsening. Single persistent kernel with software grid
// barrier (all cross-block phases), plus one memset for the dense outputs.

#define N_NODES 10240
#define N_EDGES (N_NODES * 32)
#define DIM 128
#define EPS_F 0.5f
#define NBLK 120
#define NTHR 1024

// -------- device scratch (static: no allocations allowed) --------
__device__ int            g_mr[N_NODES];
__device__ unsigned char  g_mis[N_NODES];
__device__ float          g_deg[N_NODES];
__device__ int            g_cnt_row[N_NODES];
__device__ int            g_cnt_col[N_NODES];
__device__ int            g_row_start[N_NODES + 1];
__device__ int            g_col_start[N_NODES + 1];
__device__ int            g_fill_row[N_NODES];
__device__ int            g_fill_col[N_NODES];
__device__ int            g_csr_col[N_EDGES];
__device__ float          g_csr_val[N_EDGES];
__device__ int            g_csc_row[N_EDGES];
__device__ int            g_cluster[N_NODES];
__device__ float          g_counts[N_NODES];
__device__ unsigned       g_bar_count = 0;
__device__ volatile unsigned g_bar_gen = 0;
__device__ int            g_nc[2];

// -------- software grid barrier --------
// __threadfence() on sm_103a is gpu-scope -> CCTL.IVALL flushes L1, so plain
// loads after the barrier see other blocks' pre-barrier stores.
__device__ __forceinline__ void grid_barrier() {
    __syncthreads();
    if (threadIdx.x == 0) {
        unsigned gen = g_bar_gen;
        __threadfence();  // publish this block's writes + order the gen read
        unsigned ticket = atomicInc(&g_bar_count, (unsigned)(gridDim.x - 1));
        if (ticket == (unsigned)(gridDim.x - 1)) {
            __threadfence();
            g_bar_gen = gen + 1;
        } else {
            while (g_bar_gen == gen) { }
        }
        __threadfence();  // invalidate L1 before post-barrier reads
    }
    __syncthreads();
}

// Exclusive scan of N_NODES ints by ONE block of 1024 threads.
__device__ void block_scan(const int* __restrict__ cnt, int* __restrict__ start) {
    __shared__ int sh[NTHR];
    const int t = threadIdx.x;
    const int PER = N_NODES / NTHR;  // 10
    int base = t * PER;
    int s = 0;
#pragma unroll
    for (int j = 0; j < PER; j++) s += cnt[base + j];
    sh[t] = s;
    __syncthreads();
    for (int off = 1; off < NTHR; off <<= 1) {
        int v = 0;
        if (t >= off) v = sh[t - off];
        __syncthreads();
        if (t >= off) sh[t] += v;
        __syncthreads();
    }
    int run = sh[t] - s;  // exclusive prefix
#pragma unroll
    for (int j = 0; j < PER; j++) { start[base + j] = run; run += cnt[base + j]; }
    if (t == NTHR - 1) start[N_NODES] = run;
}

__global__ void __launch_bounds__(NTHR, 1)
kmis_mega_kernel(const float* __restrict__ x,
                 const float* __restrict__ attr,
                 const float* __restrict__ u,
                 const int*   __restrict__ ei,
                 const int*   __restrict__ rnk,
                 float*       __restrict__ out)
{
    const int tid  = threadIdx.x;
    const int gtid = blockIdx.x * blockDim.x + tid;
    const int nthr = gridDim.x * blockDim.x;
    const int* row = ei;
    const int* col = ei + N_EDGES;

    float* outX = out;                                        // (N, D)
    float* adjc = out + (size_t)N_NODES * DIM;                // (N, N)
    float* omis = adjc + (size_t)N_NODES * N_NODES;           // (N,)
    float* oclu = omis + N_NODES;                             // (N,)

    // ---- phase 0: init scratch ----
    for (int i = gtid; i < N_NODES; i += nthr) {
        g_mr[i] = rnk[i];
        g_mis[i] = 0;
        g_deg[i] = 0.f;
        g_cnt_row[i] = 0; g_cnt_col[i] = 0;
        g_fill_row[i] = 0; g_fill_col[i] = 0;
        g_counts[i] = 0.f;
    }
    grid_barrier();

    // ---- phase 0b: degree + row/col histograms ----
    for (int e = gtid; e < N_EDGES; e += nthr) {
        int r = row[e], c = col[e];
        atomicAdd(&g_deg[r], attr[e]);
        atomicAdd(&g_cnt_row[r], 1);
        atomicAdd(&g_cnt_col[c], 1);
    }
    grid_barrier();

    // ---- phase 0c: prefix sums (block 0: CSR starts, block 1: CSC starts) ----
    if (blockIdx.x == 0)       block_scan(g_cnt_row, g_row_start);
    else if (blockIdx.x == 1)  block_scan(g_cnt_col, g_col_start);
    grid_barrier();

    // ---- phase 0d: fill CSR (col,val) and CSC (row) ----
    for (int e = gtid; e < N_EDGES; e += nthr) {
        int r = row[e], c = col[e];
        float d = g_deg[r];
        d = (d == 0.f) ? 1.f : d;
        float rv = (1.0f - EPS_F) * attr[e] / d;
        int p = g_row_start[r] + atomicAdd(&g_fill_row[r], 1);
        g_csr_col[p] = c;
        g_csr_val[p] = rv;
        int q = g_col_start[c] + atomicAdd(&g_fill_col[c], 1);
        g_csc_row[q] = r;
    }
    grid_barrier();

    // ---- MIS loop (pull-based, 2 grid barriers / iteration) ----
    const int wid = gtid >> 5, lane = gtid & 31, nwarp = nthr >> 5;
    for (int it = 0; it < 512; ++it) {
        // phase 1: mr' = min(mr, min over in-nbrs); mis |= (rank == mr')
        if (gtid == 0) g_nc[it & 1] = 0;
        for (int v = wid; v < N_NODES; v += nwarp) {
            int m = g_mr[v];
            int s0 = g_col_start[v], s1 = g_col_start[v + 1];
            for (int e = s0 + lane; e < s1; e += 32) m = min(m, g_mr[g_csc_row[e]]);
#pragma unroll
            for (int o = 16; o; o >>= 1) m = min(m, __shfl_xor_sync(0xffffffffu, m, o));
            if (lane == 0 && rnk[v] == m) g_mis[v] = 1;
        }
        grid_barrier();
        // phase 2: covered = mis[v] | OR in-nbr mis; mr = covered ? n : rank
        for (int v = wid; v < N_NODES; v += nwarp) {
            int cov = g_mis[v];
            int s0 = g_col_start[v], s1 = g_col_start[v + 1];
            for (int e = s0 + lane; e < s1 && !cov; e += 32) cov |= g_mis[g_csc_row[e]];
            cov = __any_sync(0xffffffffu, cov);
            if (lane == 0) {
                g_mr[v] = cov ? N_NODES : rnk[v];
                if (!cov) atomicAdd(&g_nc[it & 1], 1);
            }
        }
        grid_barrier();
        if (*(volatile int*)&g_nc[it & 1] == 0) break;
    }

    // ---- cluster phase: per-row multinomial via sorted sparse CDF traversal ----
    for (int i = gtid; i < N_NODES; i += nthr) {
        int s0 = g_row_start[i], s1 = g_row_start[i + 1];
        bool mi = (g_mis[i] != 0);

        float rowsum = 0.f;
        for (int e = s0; e < s1; ++e)
            if (g_mis[g_csr_col[e]]) rowsum += g_csr_val[e];
        if (mi) rowsum += EPS_F;
        float rs = (rowsum == 0.f) ? 1.f : rowsum;

        // pass 1: total of normalized masses in ascending-column order
        float total = 0.f;
        int prev = -1;
        while (1) {
            int jm = 0x7fffffff;
            if (mi && i > prev) jm = i;
            for (int e = s0; e < s1; ++e) {
                int c = g_csr_col[e];
                if (c > prev && c < jm && g_mis[c]) jm = c;
            }
            if (jm == 0x7fffffff) break;
            float mass = 0.f;
            for (int e = s0; e < s1; ++e)
                if (g_csr_col[e] == jm) mass += g_csr_val[e];
            if (jm == i && mi) mass += EPS_F;
            total += mass / rs;
            prev = jm;
        }
        float T = u[i] * total;

        // pass 2: first column whose normalized CDF exceeds T
        int res = 0;
        prev = -1;
        float acc = 0.f;
        while (1) {
            int jm = 0x7fffffff;
            if (mi && i > prev) jm = i;
            for (int e = s0; e < s1; ++e) {
                int c = g_csr_col[e];
                if (c > prev && c < jm && g_mis[c]) jm = c;
            }
            if (jm == 0x7fffffff) break;
            float mass = 0.f;
            for (int e = s0; e < s1; ++e)
                if (g_csr_col[e] == jm) mass += g_csr_val[e];
            if (jm == i && mi) mass += EPS_F;
            acc += mass / rs;
            if (acc > T) { res = jm; break; }
            prev = jm;
        }

        g_cluster[i] = res;
        atomicAdd(&g_counts[res], 1.0f);
        omis[i] = mi ? 1.0f : 0.0f;
        oclu[i] = (float)res;
    }
    grid_barrier();

    // ---- pooling scatter (x -> out rows by cluster) + adjacency scatter ----
    for (int idx = gtid; idx < N_NODES * (DIM / 4); idx += nthr) {
        int i = idx >> 5, q = idx & 31;
        int c = g_cluster[i];
        float4 xv = reinterpret_cast<const float4*>(x)[idx];
        float* dst = outX + (size_t)c * DIM + q * 4;
        atomicAdd(dst + 0, xv.x);
        atomicAdd(dst + 1, xv.y);
        atomicAdd(dst + 2, xv.z);
        atomicAdd(dst + 3, xv.w);
    }
    for (int e = gtid; e < N_EDGES; e += nthr) {
        int r = row[e], c = col[e];
        atomicAdd(&adjc[(size_t)g_cluster[r] * N_NODES + g_cluster[c]], attr[e]);
    }
    grid_barrier();

    // ---- divide pooled sums by max(counts, 1) ----
    for (int idx = gtid; idx < N_NODES * (DIM / 4); idx += nthr) {
        int i = idx >> 5;
        float cm = fmaxf(g_counts[i], 1.0f);
        float4 v = reinterpret_cast<float4*>(outX)[idx];
        v.x = v.x / cm; v.y = v.y / cm; v.z = v.z / cm; v.w = v.w / cm;
        reinterpret_cast<float4*>(outX)[idx] = v;
    }
}

extern "C" void kernel_launch(void* const* d_in, const int* in_sizes, int n_in,
                              void* d_out, int out_size) {
    const float* x    = (const float*)d_in[0];  // (N, D)
    const float* attr = (const float*)d_in[1];  // (E,)
    const float* u    = (const float*)d_in[2];  // (N,)
    const int*   ei   = (const int*)  d_in[3];  // (2, E)
    const int*   rnk  = (const int*)  d_in[4];  // (N,)
    float* out = (float*)d_out;

    // zero the dense output regions (out block + adj_c block); mis/cluster are
    // fully written by the kernel.
    size_t zbytes = ((size_t)N_NODES * DIM + (size_t)N_NODES * N_NODES) * sizeof(float);
    cudaMemsetAsync(d_out, 0, zbytes);

    kmis_mega_kernel<<<NBLK, NTHR>>>(x, attr, u, ei, rnk, out);
}

// round 6
// speedup vs baseline: 1.0361x; 1.0361x over previous
#include <cuda_runtime.h>
#include <cstdint>

// KMISCoarsening: persistent mega-kernel. Round-1-proven structure:
//  - atomicInc/gen grid barrier (proven)
//  - full-sweep MIS with g_nc parity exit (proven) + skip-covered fast path
//  - 425MB output zeroing interleaved into barrier arrivals
//  - FIX vs rounds 2-4: restored grid_barrier between scratch init and the
//    histogram atomics (missing barrier let blocks 10-119 accumulate into
//    arrays blocks 0-9 were still zeroing).

#define N_NODES 10240
#define N_EDGES (N_NODES * 32)
#define DIM 128
#define EPS_F 0.5f
#define NBLK 120
#define NTHR 1024

// output float4 count of region to zero: outX (N*D) + adjc (N*N)
#define NQ_ZERO ((size_t)(N_NODES * DIM + (size_t)N_NODES * N_NODES) / 4)  // 26,542,080
#define PORTION (NQ_ZERO / NBLK)   // 221,184 quads per block
#define ZQ 9216                     // quads zeroed per block per barrier slot (144KB)

// -------- device scratch (static: no allocations allowed) --------
__device__ int            g_mr[N_NODES];
__device__ unsigned char  g_mis[N_NODES];
__device__ float          g_deg[N_NODES];
__device__ int            g_cnt_row[N_NODES];
__device__ int            g_cnt_col[N_NODES];
__device__ int            g_row_start[N_NODES + 1];
__device__ int            g_col_start[N_NODES + 1];
__device__ int            g_fill_row[N_NODES];
__device__ int            g_fill_col[N_NODES];
__device__ int            g_csr_col[N_EDGES];
__device__ float          g_csr_val[N_EDGES];
__device__ int            g_csc_row[N_EDGES];
__device__ int            g_cluster[N_NODES];
__device__ float          g_counts[N_NODES];
__device__ unsigned       g_bar_count = 0;
__device__ volatile unsigned g_bar_gen = 0;
__device__ int            g_nc[2];

// -------- Round-1-proven software grid barrier --------
__device__ __forceinline__ void grid_barrier() {
    __syncthreads();
    if (threadIdx.x == 0) {
        unsigned gen = g_bar_gen;
        __threadfence();  // publish this block's writes + order the gen read
        unsigned ticket = atomicInc(&g_bar_count, (unsigned)(gridDim.x - 1));
        if (ticket == (unsigned)(gridDim.x - 1)) {
            __threadfence();
            g_bar_gen = gen + 1;
        } else {
            while (g_bar_gen == gen) { }
        }
        __threadfence();  // invalidate L1 before post-barrier reads
    }
    __syncthreads();
}

// Exclusive scan of N_NODES ints by ONE block of 1024 threads.
__device__ void block_scan(const int* __restrict__ cnt, int* __restrict__ start) {
    __shared__ int sh[NTHR];
    const int t = threadIdx.x;
    const int PER = N_NODES / NTHR;  // 10
    int base = t * PER;
    int s = 0;
#pragma unroll
    for (int j = 0; j < PER; j++) s += cnt[base + j];
    sh[t] = s;
    __syncthreads();
    for (int off = 1; off < NTHR; off <<= 1) {
        int v = 0;
        if (t >= off) v = sh[t - off];
        __syncthreads();
        if (t >= off) sh[t] += v;
        __syncthreads();
    }
    int run = sh[t] - s;  // exclusive prefix
#pragma unroll
    for (int j = 0; j < PER; j++) { start[base + j] = run; run += cnt[base + j]; }
    if (t == NTHR - 1) start[N_NODES] = run;
}

__global__ void __launch_bounds__(NTHR, 1)
kmis_mega_kernel(const float* __restrict__ x,
                 const float* __restrict__ attr,
                 const float* __restrict__ u,
                 const int*   __restrict__ ei,
                 const int*   __restrict__ rnk,
                 float*       __restrict__ out)
{
    const int tid  = threadIdx.x;
    const int gtid = blockIdx.x * blockDim.x + tid;
    const int nthr = gridDim.x * blockDim.x;
    const int* row = ei;
    const int* col = ei + N_EDGES;

    float* outX = out;                                        // (N, D)
    float* adjc = out + (size_t)N_NODES * DIM;                // (N, N)
    float* omis = adjc + (size_t)N_NODES * N_NODES;           // (N,)
    float* oclu = omis + N_NODES;                             // (N,)

    // per-block zeroing slice [zp0, zp1), local cursor zc
    float4* zdst = reinterpret_cast<float4*>(out);
    const float4 zv = make_float4(0.f, 0.f, 0.f, 0.f);
    const size_t zp0 = (size_t)blockIdx.x * PORTION;
    const size_t zp1 = zp0 + PORTION;
    size_t zc = zp0;

    // ---- phase 0: init scratch ----
    for (int i = gtid; i < N_NODES; i += nthr) {
        g_mr[i] = rnk[i];
        g_mis[i] = 0;
        g_deg[i] = 0.f;
        g_cnt_row[i] = 0; g_cnt_col[i] = 0;
        g_fill_row[i] = 0; g_fill_col[i] = 0;
        g_counts[i] = 0.f;
    }
    grid_barrier();   // REQUIRED: init must complete before histogram atomics

    // ---- phase 0b: degree + row/col histograms ----
    for (int e = gtid; e < N_EDGES; e += nthr) {
        int r = row[e], c = col[e];
        atomicAdd(&g_deg[r], attr[e]);
        atomicAdd(&g_cnt_row[r], 1);
        atomicAdd(&g_cnt_col[c], 1);
    }
    grid_barrier();

    // ---- phase 0c: prefix sums ----
    if (blockIdx.x == 0)       block_scan(g_cnt_row, g_row_start);
    else if (blockIdx.x == 1)  block_scan(g_cnt_col, g_col_start);
    grid_barrier();

    // ---- phase 0d: fill CSR (col,val) and CSC (row) ----
    for (int e = gtid; e < N_EDGES; e += nthr) {
        int r = row[e], c = col[e];
        float d = g_deg[r];
        d = (d == 0.f) ? 1.f : d;
        float rv = (1.0f - EPS_F) * attr[e] / d;
        int p = g_row_start[r] + atomicAdd(&g_fill_row[r], 1);
        g_csr_col[p] = c;
        g_csr_val[p] = rv;
        int q = g_col_start[c] + atomicAdd(&g_fill_col[c], 1);
        g_csc_row[q] = r;
    }
    grid_barrier();

    // ---- MIS loop (pull-based full sweep, skip-covered fast path) ----
    const int wid = gtid >> 5, lane = gtid & 31, nwarp = nthr >> 5;
    for (int it = 0; it < 512; ++it) {
        // phase 1: for uncovered v: m = min(rank[v], min in-nbr mr); mis if m==rank
        if (gtid == 0) g_nc[it & 1] = 0;
        for (int v = wid; v < N_NODES; v += nwarp) {
            int m = g_mr[v];
            if (m == N_NODES) continue;  // covered: can never join MIS
            int s0 = g_col_start[v], s1 = g_col_start[v + 1];
            for (int e = s0 + lane; e < s1; e += 32) m = min(m, g_mr[g_csc_row[e]]);
#pragma unroll
            for (int o = 16; o; o >>= 1) m = min(m, __shfl_xor_sync(0xffffffffu, m, o));
            if (lane == 0 && rnk[v] == m) g_mis[v] = 1;
        }
        // interleaved zero slice (posted stores drain during barrier spin)
        {
            size_t zend = zc + ZQ; if (zend > zp1) zend = zp1;
            for (size_t i = zc + tid; i < zend; i += NTHR) __stcs(zdst + i, zv);
            zc = zend;
        }
        grid_barrier();
        // phase 2: coverage for uncovered v; covered stay covered
        for (int v = wid; v < N_NODES; v += nwarp) {
            if (g_mr[v] == N_NODES) continue;  // stays covered, not counted
            int cov = g_mis[v];
            int s0 = g_col_start[v], s1 = g_col_start[v + 1];
            for (int e = s0 + lane; e < s1 && !cov; e += 32) cov |= g_mis[g_csc_row[e]];
            cov = __any_sync(0xffffffffu, cov);
            if (lane == 0) {
                if (cov) g_mr[v] = N_NODES;
                else     atomicAdd(&g_nc[it & 1], 1);
            }
        }
        // interleaved zero slice
        {
            size_t zend = zc + ZQ; if (zend > zp1) zend = zp1;
            for (size_t i = zc + tid; i < zend; i += NTHR) __stcs(zdst + i, zv);
            zc = zend;
        }
        grid_barrier();
        if (*(volatile int*)&g_nc[it & 1] == 0) break;
    }

    // ---- finish this block's zero slice (drains during cluster phase) ----
    for (size_t i = zc + tid; i < zp1; i += NTHR) __stcs(zdst + i, zv);

    // ---- cluster phase: per-row multinomial via sorted sparse CDF traversal ----
    for (int i = gtid; i < N_NODES; i += nthr) {
        int s0 = g_row_start[i], s1 = g_row_start[i + 1];
        bool mi = (g_mis[i] != 0);

        float rowsum = 0.f;
        for (int e = s0; e < s1; ++e)
            if (g_mis[g_csr_col[e]]) rowsum += g_csr_val[e];
        if (mi) rowsum += EPS_F;
        float rs = (rowsum == 0.f) ? 1.f : rowsum;

        // pass 1: total of normalized masses in ascending-column order
        float total = 0.f;
        int prev = -1;
        while (1) {
            int jm = 0x7fffffff;
            if (mi && i > prev) jm = i;
            for (int e = s0; e < s1; ++e) {
                int c = g_csr_col[e];
                if (c > prev && c < jm && g_mis[c]) jm = c;
            }
            if (jm == 0x7fffffff) break;
            float mass = 0.f;
            for (int e = s0; e < s1; ++e)
                if (g_csr_col[e] == jm) mass += g_csr_val[e];
            if (jm == i && mi) mass += EPS_F;
            total += mass / rs;
            prev = jm;
        }
        float T = u[i] * total;

        // pass 2: first column whose normalized CDF exceeds T
        int res = 0;
        prev = -1;
        float acc = 0.f;
        while (1) {
            int jm = 0x7fffffff;
            if (mi && i > prev) jm = i;
            for (int e = s0; e < s1; ++e) {
                int c = g_csr_col[e];
                if (c > prev && c < jm && g_mis[c]) jm = c;
            }
            if (jm == 0x7fffffff) break;
            float mass = 0.f;
            for (int e = s0; e < s1; ++e)
                if (g_csr_col[e] == jm) mass += g_csr_val[e];
            if (jm == i && mi) mass += EPS_F;
            acc += mass / rs;
            if (acc > T) { res = jm; break; }
            prev = jm;
        }

        g_cluster[i] = res;
        atomicAdd(&g_counts[res], 1.0f);
        omis[i] = mi ? 1.0f : 0.0f;
        oclu[i] = (float)res;
    }
    grid_barrier();

    // ---- pooling scatter (x -> out rows by cluster) + adjacency scatter ----
    for (int idx = gtid; idx < N_NODES * (DIM / 4); idx += nthr) {
        int i = idx >> 5, q = idx & 31;
        int c = g_cluster[i];
        float4 xv = reinterpret_cast<const float4*>(x)[idx];
        float* dst = outX + (size_t)c * DIM + q * 4;
        atomicAdd(dst + 0, xv.x);
        atomicAdd(dst + 1, xv.y);
        atomicAdd(dst + 2, xv.z);
        atomicAdd(dst + 3, xv.w);
    }
    for (int e = gtid; e < N_EDGES; e += nthr) {
        int r = row[e], c = col[e];
        atomicAdd(&adjc[(size_t)g_cluster[r] * N_NODES + g_cluster[c]], attr[e]);
    }
    grid_barrier();

    // ---- divide pooled sums by max(counts, 1) ----
    for (int idx = gtid; idx < N_NODES * (DIM / 4); idx += nthr) {
        int i = idx >> 5;
        float cm = fmaxf(g_counts[i], 1.0f);
        float4 v = reinterpret_cast<float4*>(outX)[idx];
        v.x = v.x / cm; v.y = v.y / cm; v.z = v.z / cm; v.w = v.w / cm;
        reinterpret_cast<float4*>(outX)[idx] = v;
    }
}

extern "C" void kernel_launch(void* const* d_in, const int* in_sizes, int n_in,
                              void* d_out, int out_size) {
    const float* x    = (const float*)d_in[0];  // (N, D)
    const float* attr = (const float*)d_in[1];  // (E,)
    const float* u    = (const float*)d_in[2];  // (N,)
    const int*   ei   = (const int*)  d_in[3];  // (2, E)
    const int*   rnk  = (const int*)  d_in[4];  // (N,)
    float* out = (float*)d_out;

    kmis_mega_kernel<<<NBLK, NTHR>>>(x, attr, u, ei, rnk, out);
}